// round 3
// baseline (speedup 1.0000x reference)
#include <cuda_runtime.h>
#include <cuda_bf16.h>
#include <cstdint>

// ---------------- problem constants ----------------
#define N_NODES   100000
#define N_EDGES   1600000
#define NUM_GRAPHS 1024
#define IN_FEAT   7
#define H         128
#define BN_EPS    1e-5f

// ---------------- scratch (device globals, no allocation) ----------------
__device__ __align__(256) float g_agg[(size_t)N_NODES * H];     // also used as N x 8 for layer 0
__device__ __align__(256) float g_z[(size_t)N_NODES * H];
__device__ __align__(256) float g_cat[(size_t)N_NODES * 3 * H]; // layer outputs side by side
__device__ __align__(256) float g_pool[(size_t)NUM_GRAPHS * 3 * H];
__device__ __align__(256) float g_hid[(size_t)NUM_GRAPHS * 2 * H];

// ---------------- helpers ----------------
__device__ __forceinline__ void red_add_v4(float* addr, float4 v) {
    asm volatile("red.global.add.v4.f32 [%0], {%1, %2, %3, %4};"
                 :: "l"(addr), "f"(v.x), "f"(v.y), "f"(v.z), "f"(v.w)
                 : "memory");
}

// ---------------- layer 0: scatter of 7-dim raw features ----------------
__global__ void scatter7_kernel(const float* __restrict__ x,
                                const int* __restrict__ src,
                                const int* __restrict__ dst,
                                float* __restrict__ agg, int E)
{
    int e = blockIdx.x * blockDim.x + threadIdx.x;
    if (e >= E) return;
    int s = src[e];
    int d = dst[e];
    const float* xr = x + (size_t)s * IN_FEAT;
    float* ar = agg + (size_t)d * 8;
    #pragma unroll
    for (int k = 0; k < IN_FEAT; k++) atomicAdd(ar + k, xr[k]);
}

// z = relu((x + agg7) @ w[7x128] + b)   -> z [N x 128]
__global__ void l0_mlp1_kernel(const float* __restrict__ x,
                               const float* __restrict__ agg,
                               const float* __restrict__ w,
                               const float* __restrict__ b,
                               float* __restrict__ z, int N)
{
    __shared__ float s_in[4][IN_FEAT];
    int tid = threadIdx.x;               // 512 threads: 4 rows x 128 cols
    int r_local = tid >> 7;
    int c = tid & 127;
    int row = blockIdx.x * 4 + r_local;
    if (tid < 4 * IN_FEAT) {
        int rr = tid / IN_FEAT, k = tid % IN_FEAT;
        int gr = blockIdx.x * 4 + rr;
        if (gr < N) s_in[rr][k] = x[(size_t)gr * IN_FEAT + k] + agg[(size_t)gr * 8 + k];
    }
    __syncthreads();
    if (row < N) {
        float acc = b[c];
        #pragma unroll
        for (int k = 0; k < IN_FEAT; k++) acc += s_in[r_local][k] * __ldg(w + k * H + c);
        z[(size_t)row * H + c] = fmaxf(acc, 0.f);
    }
}

// ---------------- scatter for H=128 features (one warp per edge) ----------------
__global__ void scatter128_kernel(const float* __restrict__ h, int ldH,
                                  const int* __restrict__ src,
                                  const int* __restrict__ dst,
                                  float* __restrict__ agg, int E)
{
    int gw = (blockIdx.x * blockDim.x + threadIdx.x) >> 5;
    int lane = threadIdx.x & 31;
    if (gw >= E) return;
    int s = src[gw];
    int d = dst[gw];
    const float4* hp = reinterpret_cast<const float4*>(h + (size_t)s * ldH);
    float4 v = hp[lane];
    red_add_v4(agg + (size_t)d * H + lane * 4, v);
}

// ---------------- 128-wide SGEMM: C = relu((A [+A2]) @ B + bias) ----------------
// A: N x 128 with row stride ldA, A2 optional (row stride 128), B: 128x128,
// C: N x 128 with row stride ldC. 256 threads, 128x128 tile, 8x8 per thread.
__global__ void __launch_bounds__(256, 2)
gemm128_kernel(const float* __restrict__ A, int ldA,
               const float* __restrict__ A2,
               const float* __restrict__ B,
               const float* __restrict__ bias,
               float* __restrict__ C, int ldC, int N)
{
    __shared__ float As[16][128];
    __shared__ float Bs[16][128];
    int tid = threadIdx.x;
    int tx = tid & 15, ty = tid >> 4;
    int m0 = blockIdx.x * 128;

    float acc[8][8];
    #pragma unroll
    for (int i = 0; i < 8; i++)
        #pragma unroll
        for (int j = 0; j < 8; j++) acc[i][j] = 0.f;

    for (int kt = 0; kt < H; kt += 16) {
        // load A tile (128 rows x 16 k) into As transposed [k][row]
        #pragma unroll
        for (int u = 0; u < 2; u++) {
            int i = tid + u * 256;
            int row = i >> 2;
            int c4 = (i & 3) * 4;
            float4 v = make_float4(0.f, 0.f, 0.f, 0.f);
            int gr = m0 + row;
            if (gr < N) {
                v = *reinterpret_cast<const float4*>(A + (size_t)gr * ldA + kt + c4);
                if (A2) {
                    float4 w = *reinterpret_cast<const float4*>(A2 + (size_t)gr * H + kt + c4);
                    v.x += w.x; v.y += w.y; v.z += w.z; v.w += w.w;
                }
            }
            As[c4 + 0][row] = v.x;
            As[c4 + 1][row] = v.y;
            As[c4 + 2][row] = v.z;
            As[c4 + 3][row] = v.w;
        }
        // load B tile (16 k x 128 cols)
        #pragma unroll
        for (int u = 0; u < 2; u++) {
            int i = tid + u * 256;
            int kr = i >> 5;
            int c4 = (i & 31) * 4;
            *reinterpret_cast<float4*>(&Bs[kr][c4]) =
                *reinterpret_cast<const float4*>(B + (size_t)(kt + kr) * H + c4);
        }
        __syncthreads();
        #pragma unroll
        for (int k = 0; k < 16; k++) {
            float ra[8], rb[8];
            #pragma unroll
            for (int i = 0; i < 8; i++) ra[i] = As[k][ty * 8 + i];
            #pragma unroll
            for (int j = 0; j < 8; j++) rb[j] = Bs[k][tx * 8 + j];
            #pragma unroll
            for (int i = 0; i < 8; i++)
                #pragma unroll
                for (int j = 0; j < 8; j++) acc[i][j] += ra[i] * rb[j];
        }
        __syncthreads();
    }

    // epilogue: bias + relu
    #pragma unroll
    for (int i = 0; i < 8; i++) {
        int gr = m0 + ty * 8 + i;
        if (gr < N) {
            #pragma unroll
            for (int j4 = 0; j4 < 2; j4++) {
                int j0 = tx * 8 + j4 * 4;
                float4 o;
                o.x = fmaxf(acc[i][j4 * 4 + 0] + bias[j0 + 0], 0.f);
                o.y = fmaxf(acc[i][j4 * 4 + 1] + bias[j0 + 1], 0.f);
                o.z = fmaxf(acc[i][j4 * 4 + 2] + bias[j0 + 2], 0.f);
                o.w = fmaxf(acc[i][j4 * 4 + 3] + bias[j0 + 3], 0.f);
                *reinterpret_cast<float4*>(C + (size_t)gr * ldC + j0) = o;
            }
        }
    }
}

// ---------------- global add pool over sorted batch ids ----------------
__global__ void pool_kernel(const float* __restrict__ cat,
                            const int* __restrict__ batch,
                            float* __restrict__ pool, int N)
{
    int t = blockIdx.x * blockDim.x + threadIdx.x;
    int total = N * 96;                 // 384 floats = 96 float4 per node
    if (t >= total) return;
    int n = t / 96;
    int q = t % 96;
    int g = batch[n];
    float4 v = reinterpret_cast<const float4*>(cat)[(size_t)n * 96 + q];
    red_add_v4(pool + (size_t)g * 384 + q * 4, v);
}

// ---------------- classifier layer 1: 384 -> 256 + BN + relu ----------------
__global__ void clf1_kernel(const float* __restrict__ pool,
                            const float* __restrict__ w,
                            const float* __restrict__ b,
                            const float* __restrict__ gamma,
                            const float* __restrict__ beta,
                            const float* __restrict__ mean,
                            const float* __restrict__ var,
                            float* __restrict__ hid)
{
    __shared__ float sp[384];
    int g = blockIdx.x;
    int j = threadIdx.x;                 // 256
    for (int i = j; i < 384; i += 256) sp[i] = pool[(size_t)g * 384 + i];
    __syncthreads();
    float acc = b[j];
    #pragma unroll 8
    for (int k = 0; k < 384; k++) acc += sp[k] * __ldg(w + (size_t)k * 256 + j);
    acc = (acc - mean[j]) * rsqrtf(var[j] + BN_EPS) * gamma[j] + beta[j];
    hid[(size_t)g * 256 + j] = fmaxf(acc, 0.f);
}

// ---------------- classifier layer 2: 256 -> 2 ----------------
__global__ void clf2_kernel(const float* __restrict__ hid,
                            const float* __restrict__ w,
                            const float* __restrict__ b,
                            float* __restrict__ out)
{
    int t = blockIdx.x * blockDim.x + threadIdx.x;
    if (t >= NUM_GRAPHS * 2) return;
    int g = t >> 1, j = t & 1;
    float acc = b[j];
    const float* hr = hid + (size_t)g * 256;
    #pragma unroll 8
    for (int k = 0; k < 256; k++) acc += hr[k] * __ldg(w + k * 2 + j);
    out[t] = acc;
}

// ---------------- launch ----------------
extern "C" void kernel_launch(void* const* d_in, const int* in_sizes, int n_in,
                              void* d_out, int out_size)
{
    const float* x      = (const float*)d_in[0];
    const int*   ei     = (const int*)d_in[1];
    const int*   batch  = (const int*)d_in[2];
    // per-layer weights: w1_l, b1_l, w2_l, b2_l at indices 3 + 4*l
    const float* w1[3], *b1[3], *w2[3], *b2[3];
    for (int l = 0; l < 3; l++) {
        w1[l] = (const float*)d_in[3 + 4 * l + 0];
        b1[l] = (const float*)d_in[3 + 4 * l + 1];
        w2[l] = (const float*)d_in[3 + 4 * l + 2];
        b2[l] = (const float*)d_in[3 + 4 * l + 3];
    }
    const float* clf_w1 = (const float*)d_in[15];
    const float* clf_b1 = (const float*)d_in[16];
    const float* clf_w2 = (const float*)d_in[17];
    const float* clf_b2 = (const float*)d_in[18];
    const float* bn_g   = (const float*)d_in[19];
    const float* bn_b   = (const float*)d_in[20];
    const float* bn_m   = (const float*)d_in[21];
    const float* bn_v   = (const float*)d_in[22];
    float* out = (float*)d_out;

    const int N = in_sizes[0] / IN_FEAT;     // 100000
    const int E = in_sizes[1] / 2;           // 1600000

    float *d_agg, *d_z, *d_cat, *d_pool, *d_hid;
    cudaGetSymbolAddress((void**)&d_agg, g_agg);
    cudaGetSymbolAddress((void**)&d_z, g_z);
    cudaGetSymbolAddress((void**)&d_cat, g_cat);
    cudaGetSymbolAddress((void**)&d_pool, g_pool);
    cudaGetSymbolAddress((void**)&d_hid, g_hid);

    const int* src = ei;
    const int* dst = ei + E;

    const int gemm_blocks = (N + 127) / 128;

    // ---- layer 0 ----
    cudaMemsetAsync(d_agg, 0, (size_t)N * 8 * sizeof(float));
    scatter7_kernel<<<(E + 255) / 256, 256>>>(x, src, dst, d_agg, E);
    l0_mlp1_kernel<<<(N + 3) / 4, 512>>>(x, d_agg, w1[0], b1[0], d_z, N);
    gemm128_kernel<<<gemm_blocks, 256>>>(d_z, H, nullptr, w2[0], b2[0],
                                         d_cat + 0, 3 * H, N);

    // ---- layers 1, 2 ----
    for (int l = 1; l < 3; l++) {
        const float* h_prev = d_cat + (size_t)(l - 1) * H;  // row stride 384
        cudaMemsetAsync(d_agg, 0, (size_t)N * H * sizeof(float));
        scatter128_kernel<<<(E * 32 + 255) / 256, 256>>>(h_prev, 3 * H, src, dst, d_agg, E);
        gemm128_kernel<<<gemm_blocks, 256>>>(h_prev, 3 * H, d_agg, w1[l], b1[l],
                                             d_z, H, N);
        gemm128_kernel<<<gemm_blocks, 256>>>(d_z, H, nullptr, w2[l], b2[l],
                                             d_cat + (size_t)l * H, 3 * H, N);
    }

    // ---- global add pool ----
    cudaMemsetAsync(d_pool, 0, (size_t)NUM_GRAPHS * 384 * sizeof(float));
    pool_kernel<<<(N * 96 + 255) / 256, 256>>>(d_cat, batch, d_pool, N);

    // ---- classifier ----
    clf1_kernel<<<NUM_GRAPHS, 256>>>(d_pool, clf_w1, clf_b1, bn_g, bn_b, bn_m, bn_v, d_hid);
    clf2_kernel<<<(NUM_GRAPHS * 2 + 255) / 256, 256>>>(d_hid, clf_w2, clf_b2, out);
}

// round 4
// speedup vs baseline: 1.1972x; 1.1972x over previous
#include <cuda_runtime.h>
#include <cuda_bf16.h>
#include <cstdint>

// ---------------- problem constants ----------------
#define N_NODES   100000
#define N_EDGES   1600000
#define NUM_GRAPHS 1024
#define IN_FEAT   7
#define H         128
#define BN_EPS    1e-5f

// ---------------- scratch (device globals, no allocation) ----------------
__device__ __align__(256) float g_agg[(size_t)N_NODES * H];     // also used as N x 8 for layer 0
__device__ __align__(256) float g_cat[(size_t)N_NODES * 3 * H]; // layer outputs side by side
__device__ __align__(256) float g_pool[(size_t)NUM_GRAPHS * 3 * H];
__device__ __align__(256) float g_hid[(size_t)NUM_GRAPHS * 2 * H];

// ---------------- helpers ----------------
__device__ __forceinline__ void red_add_v4(float* addr, float4 v) {
    asm volatile("red.global.add.v4.f32 [%0], {%1, %2, %3, %4};"
                 :: "l"(addr), "f"(v.x), "f"(v.y), "f"(v.z), "f"(v.w)
                 : "memory");
}

// ---------------- layer 0: scatter of 7-dim raw features ----------------
__global__ void scatter7_kernel(const float* __restrict__ x,
                                const int* __restrict__ src,
                                const int* __restrict__ dst,
                                float* __restrict__ agg, int E)
{
    int e = blockIdx.x * blockDim.x + threadIdx.x;
    if (e >= E) return;
    int s = src[e];
    int d = dst[e];
    const float* xr = x + (size_t)s * IN_FEAT;
    float* ar = agg + (size_t)d * 8;
    #pragma unroll
    for (int k = 0; k < IN_FEAT; k++) atomicAdd(ar + k, xr[k]);
}

// ---------------- scatter for H=128 features: 4 edges per warp (MLP=4) ---------
__global__ void scatter128_kernel(const float* __restrict__ h, int ldH,
                                  const int* __restrict__ src,
                                  const int* __restrict__ dst,
                                  float* __restrict__ agg, int E)
{
    int warp = (blockIdx.x * blockDim.x + threadIdx.x) >> 5;
    int lane = threadIdx.x & 31;
    int e0 = warp * 4;
    if (e0 >= E) return;

    int s[4], d[4];
    #pragma unroll
    for (int i = 0; i < 4; i++) {
        int e = (e0 + i < E) ? (e0 + i) : (E - 1);
        s[i] = __ldg(src + e);
        d[i] = __ldg(dst + e);
    }
    float4 v[4];
    #pragma unroll
    for (int i = 0; i < 4; i++)
        v[i] = *reinterpret_cast<const float4*>(h + (size_t)s[i] * ldH + lane * 4);
    #pragma unroll
    for (int i = 0; i < 4; i++)
        if (e0 + i < E)
            red_add_v4(agg + (size_t)d[i] * H + lane * 4, v[i]);
}

// ---------------- fused GIN MLP (layers 1,2): C = relu(relu((A1+A2)@B1+b1)@B2+b2)
// A1: N x 128 (row stride ldA), A2: N x 128 (row stride H). C: row stride ldC.
// smem: z_s[128*128] | As[16*128] | Bs[16*128]  = 81920 bytes
__global__ void __launch_bounds__(256, 2)
fused_mlp_kernel(const float* __restrict__ A1, int ldA,
                 const float* __restrict__ A2,
                 const float* __restrict__ B1, const float* __restrict__ b1,
                 const float* __restrict__ B2, const float* __restrict__ b2,
                 float* __restrict__ C, int ldC, int N)
{
    extern __shared__ float sm[];
    float* z_s = sm;                 // 128 x 128
    float* As  = sm + 16384;         // 16 x 128 (k-major)
    float* Bs  = As + 2048;          // 16 x 128

    int tid = threadIdx.x;
    int tx = tid & 15, ty = tid >> 4;
    int m0 = blockIdx.x * 128;

    float acc[8][8];
    #pragma unroll
    for (int i = 0; i < 8; i++)
        #pragma unroll
        for (int j = 0; j < 8; j++) acc[i][j] = 0.f;

    // ---- phase 1: z = relu((A1+A2) @ B1 + b1) ----
    for (int kt = 0; kt < H; kt += 16) {
        #pragma unroll
        for (int u = 0; u < 2; u++) {
            int i = tid + u * 256;
            int row = i >> 2;
            int c4 = (i & 3) * 4;
            float4 v = make_float4(0.f, 0.f, 0.f, 0.f);
            int gr = m0 + row;
            if (gr < N) {
                v = *reinterpret_cast<const float4*>(A1 + (size_t)gr * ldA + kt + c4);
                float4 w = *reinterpret_cast<const float4*>(A2 + (size_t)gr * H + kt + c4);
                v.x += w.x; v.y += w.y; v.z += w.z; v.w += w.w;
            }
            As[(c4 + 0) * 128 + row] = v.x;
            As[(c4 + 1) * 128 + row] = v.y;
            As[(c4 + 2) * 128 + row] = v.z;
            As[(c4 + 3) * 128 + row] = v.w;
        }
        #pragma unroll
        for (int u = 0; u < 2; u++) {
            int i = tid + u * 256;
            int kr = i >> 5;
            int c4 = (i & 31) * 4;
            *reinterpret_cast<float4*>(&Bs[kr * 128 + c4]) =
                *reinterpret_cast<const float4*>(B1 + (size_t)(kt + kr) * H + c4);
        }
        __syncthreads();
        #pragma unroll
        for (int k = 0; k < 16; k++) {
            float ra[8], rb[8];
            #pragma unroll
            for (int i = 0; i < 8; i++) ra[i] = As[k * 128 + ty * 8 + i];
            #pragma unroll
            for (int j = 0; j < 8; j++) rb[j] = Bs[k * 128 + tx * 8 + j];
            #pragma unroll
            for (int i = 0; i < 8; i++)
                #pragma unroll
                for (int j = 0; j < 8; j++) acc[i][j] += ra[i] * rb[j];
        }
        __syncthreads();
    }

    // epilogue 1: bias + relu -> z_s[row][col]
    #pragma unroll
    for (int i = 0; i < 8; i++) {
        int r = ty * 8 + i;
        #pragma unroll
        for (int j4 = 0; j4 < 2; j4++) {
            int j0 = tx * 8 + j4 * 4;
            float4 o;
            o.x = fmaxf(acc[i][j4 * 4 + 0] + b1[j0 + 0], 0.f);
            o.y = fmaxf(acc[i][j4 * 4 + 1] + b1[j0 + 1], 0.f);
            o.z = fmaxf(acc[i][j4 * 4 + 2] + b1[j0 + 2], 0.f);
            o.w = fmaxf(acc[i][j4 * 4 + 3] + b1[j0 + 3], 0.f);
            *reinterpret_cast<float4*>(&z_s[r * 128 + j0]) = o;
        }
    }

    // ---- phase 2: C = relu(z @ B2 + b2) ----
    float acc2[8][8];
    #pragma unroll
    for (int i = 0; i < 8; i++)
        #pragma unroll
        for (int j = 0; j < 8; j++) acc2[i][j] = 0.f;

    for (int kt = 0; kt < H; kt += 16) {
        #pragma unroll
        for (int u = 0; u < 2; u++) {
            int i = tid + u * 256;
            int kr = i >> 5;
            int c4 = (i & 31) * 4;
            *reinterpret_cast<float4*>(&Bs[kr * 128 + c4]) =
                *reinterpret_cast<const float4*>(B2 + (size_t)(kt + kr) * H + c4);
        }
        __syncthreads();
        #pragma unroll
        for (int k = 0; k < 16; k++) {
            float ra[8], rb[8];
            #pragma unroll
            for (int i = 0; i < 8; i++) ra[i] = z_s[(ty * 8 + i) * 128 + kt + k];
            #pragma unroll
            for (int j = 0; j < 8; j++) rb[j] = Bs[k * 128 + tx * 8 + j];
            #pragma unroll
            for (int i = 0; i < 8; i++)
                #pragma unroll
                for (int j = 0; j < 8; j++) acc2[i][j] += ra[i] * rb[j];
        }
        __syncthreads();
    }

    // epilogue 2: bias + relu -> C
    #pragma unroll
    for (int i = 0; i < 8; i++) {
        int gr = m0 + ty * 8 + i;
        if (gr < N) {
            #pragma unroll
            for (int j4 = 0; j4 < 2; j4++) {
                int j0 = tx * 8 + j4 * 4;
                float4 o;
                o.x = fmaxf(acc2[i][j4 * 4 + 0] + b2[j0 + 0], 0.f);
                o.y = fmaxf(acc2[i][j4 * 4 + 1] + b2[j0 + 1], 0.f);
                o.z = fmaxf(acc2[i][j4 * 4 + 2] + b2[j0 + 2], 0.f);
                o.w = fmaxf(acc2[i][j4 * 4 + 3] + b2[j0 + 3], 0.f);
                *reinterpret_cast<float4*>(C + (size_t)gr * ldC + j0) = o;
            }
        }
    }
}

// ---------------- fused layer-0 MLP: K1 = 7 ----------------
// smem: z_s[128*128] | in_s[128*8] | Bs[16*128] = 77824 bytes
__global__ void __launch_bounds__(256, 2)
fused_l0_kernel(const float* __restrict__ x,
                const float* __restrict__ agg7,
                const float* __restrict__ B1, const float* __restrict__ b1,
                const float* __restrict__ B2, const float* __restrict__ b2,
                float* __restrict__ C, int ldC, int N)
{
    extern __shared__ float sm[];
    float* z_s  = sm;                 // 128 x 128
    float* in_s = sm + 16384;         // 128 x 8
    float* Bs   = in_s + 1024;        // 16 x 128 (holds B1 7x128, then B2 tiles)

    int tid = threadIdx.x;
    int tx = tid & 15, ty = tid >> 4;
    int m0 = blockIdx.x * 128;

    // load inputs (x + agg) for 128 rows x 7 feats
    for (int i = tid; i < 128 * IN_FEAT; i += 256) {
        int r = i / IN_FEAT, k = i % IN_FEAT;
        int gr = m0 + r;
        in_s[r * 8 + k] = (gr < N)
            ? x[(size_t)gr * IN_FEAT + k] + agg7[(size_t)gr * 8 + k] : 0.f;
    }
    // load B1 (7 x 128)
    for (int i = tid; i < IN_FEAT * H; i += 256) Bs[i] = B1[i];
    __syncthreads();

    // phase 1: z = relu(in @ B1 + b1)
    float acc[8][8];
    #pragma unroll
    for (int i = 0; i < 8; i++)
        #pragma unroll
        for (int j = 0; j < 8; j++) acc[i][j] = 0.f;

    #pragma unroll
    for (int k = 0; k < IN_FEAT; k++) {
        float ra[8], rb[8];
        #pragma unroll
        for (int i = 0; i < 8; i++) ra[i] = in_s[(ty * 8 + i) * 8 + k];
        #pragma unroll
        for (int j = 0; j < 8; j++) rb[j] = Bs[k * 128 + tx * 8 + j];
        #pragma unroll
        for (int i = 0; i < 8; i++)
            #pragma unroll
            for (int j = 0; j < 8; j++) acc[i][j] += ra[i] * rb[j];
    }

    #pragma unroll
    for (int i = 0; i < 8; i++) {
        int r = ty * 8 + i;
        #pragma unroll
        for (int j4 = 0; j4 < 2; j4++) {
            int j0 = tx * 8 + j4 * 4;
            float4 o;
            o.x = fmaxf(acc[i][j4 * 4 + 0] + b1[j0 + 0], 0.f);
            o.y = fmaxf(acc[i][j4 * 4 + 1] + b1[j0 + 1], 0.f);
            o.z = fmaxf(acc[i][j4 * 4 + 2] + b1[j0 + 2], 0.f);
            o.w = fmaxf(acc[i][j4 * 4 + 3] + b1[j0 + 3], 0.f);
            *reinterpret_cast<float4*>(&z_s[r * 128 + j0]) = o;
        }
    }
    __syncthreads();   // Bs reads (B1) done before phase-2 overwrite

    // phase 2: C = relu(z @ B2 + b2)
    float acc2[8][8];
    #pragma unroll
    for (int i = 0; i < 8; i++)
        #pragma unroll
        for (int j = 0; j < 8; j++) acc2[i][j] = 0.f;

    for (int kt = 0; kt < H; kt += 16) {
        #pragma unroll
        for (int u = 0; u < 2; u++) {
            int i = tid + u * 256;
            int kr = i >> 5;
            int c4 = (i & 31) * 4;
            *reinterpret_cast<float4*>(&Bs[kr * 128 + c4]) =
                *reinterpret_cast<const float4*>(B2 + (size_t)(kt + kr) * H + c4);
        }
        __syncthreads();
        #pragma unroll
        for (int k = 0; k < 16; k++) {
            float ra[8], rb[8];
            #pragma unroll
            for (int i = 0; i < 8; i++) ra[i] = z_s[(ty * 8 + i) * 128 + kt + k];
            #pragma unroll
            for (int j = 0; j < 8; j++) rb[j] = Bs[k * 128 + tx * 8 + j];
            #pragma unroll
            for (int i = 0; i < 8; i++)
                #pragma unroll
                for (int j = 0; j < 8; j++) acc2[i][j] += ra[i] * rb[j];
        }
        __syncthreads();
    }

    #pragma unroll
    for (int i = 0; i < 8; i++) {
        int gr = m0 + ty * 8 + i;
        if (gr < N) {
            #pragma unroll
            for (int j4 = 0; j4 < 2; j4++) {
                int j0 = tx * 8 + j4 * 4;
                float4 o;
                o.x = fmaxf(acc2[i][j4 * 4 + 0] + b2[j0 + 0], 0.f);
                o.y = fmaxf(acc2[i][j4 * 4 + 1] + b2[j0 + 1], 0.f);
                o.z = fmaxf(acc2[i][j4 * 4 + 2] + b2[j0 + 2], 0.f);
                o.w = fmaxf(acc2[i][j4 * 4 + 3] + b2[j0 + 3], 0.f);
                *reinterpret_cast<float4*>(C + (size_t)gr * ldC + j0) = o;
            }
        }
    }
}

// ---------------- global add pool over batch ids ----------------
__global__ void pool_kernel(const float* __restrict__ cat,
                            const int* __restrict__ batch,
                            float* __restrict__ pool, int N)
{
    int t = blockIdx.x * blockDim.x + threadIdx.x;
    int total = N * 96;                 // 384 floats = 96 float4 per node
    if (t >= total) return;
    int n = t / 96;
    int q = t % 96;
    int g = batch[n];
    float4 v = reinterpret_cast<const float4*>(cat)[(size_t)n * 96 + q];
    red_add_v4(pool + (size_t)g * 384 + q * 4, v);
}

// ---------------- classifier layer 1: 384 -> 256 + BN + relu ----------------
__global__ void clf1_kernel(const float* __restrict__ pool,
                            const float* __restrict__ w,
                            const float* __restrict__ b,
                            const float* __restrict__ gamma,
                            const float* __restrict__ beta,
                            const float* __restrict__ mean,
                            const float* __restrict__ var,
                            float* __restrict__ hid)
{
    __shared__ float sp[384];
    int g = blockIdx.x;
    int j = threadIdx.x;                 // 256
    for (int i = j; i < 384; i += 256) sp[i] = pool[(size_t)g * 384 + i];
    __syncthreads();
    float acc = b[j];
    #pragma unroll 8
    for (int k = 0; k < 384; k++) acc += sp[k] * __ldg(w + (size_t)k * 256 + j);
    acc = (acc - mean[j]) * rsqrtf(var[j] + BN_EPS) * gamma[j] + beta[j];
    hid[(size_t)g * 256 + j] = fmaxf(acc, 0.f);
}

// ---------------- classifier layer 2: 256 -> 2 ----------------
__global__ void clf2_kernel(const float* __restrict__ hid,
                            const float* __restrict__ w,
                            const float* __restrict__ b,
                            float* __restrict__ out)
{
    int t = blockIdx.x * blockDim.x + threadIdx.x;
    if (t >= NUM_GRAPHS * 2) return;
    int g = t >> 1, j = t & 1;
    float acc = b[j];
    const float* hr = hid + (size_t)g * 256;
    #pragma unroll 8
    for (int k = 0; k < 256; k++) acc += hr[k] * __ldg(w + k * 2 + j);
    out[t] = acc;
}

// ---------------- launch ----------------
extern "C" void kernel_launch(void* const* d_in, const int* in_sizes, int n_in,
                              void* d_out, int out_size)
{
    const float* x      = (const float*)d_in[0];
    const int*   ei     = (const int*)d_in[1];
    const int*   batch  = (const int*)d_in[2];
    const float* w1[3], *b1[3], *w2[3], *b2[3];
    for (int l = 0; l < 3; l++) {
        w1[l] = (const float*)d_in[3 + 4 * l + 0];
        b1[l] = (const float*)d_in[3 + 4 * l + 1];
        w2[l] = (const float*)d_in[3 + 4 * l + 2];
        b2[l] = (const float*)d_in[3 + 4 * l + 3];
    }
    const float* clf_w1 = (const float*)d_in[15];
    const float* clf_b1 = (const float*)d_in[16];
    const float* clf_w2 = (const float*)d_in[17];
    const float* clf_b2 = (const float*)d_in[18];
    const float* bn_g   = (const float*)d_in[19];
    const float* bn_b   = (const float*)d_in[20];
    const float* bn_m   = (const float*)d_in[21];
    const float* bn_v   = (const float*)d_in[22];
    float* out = (float*)d_out;

    const int N = in_sizes[0] / IN_FEAT;     // 100000
    const int E = in_sizes[1] / 2;           // 1600000

    float *d_agg, *d_cat, *d_pool, *d_hid;
    cudaGetSymbolAddress((void**)&d_agg, g_agg);
    cudaGetSymbolAddress((void**)&d_cat, g_cat);
    cudaGetSymbolAddress((void**)&d_pool, g_pool);
    cudaGetSymbolAddress((void**)&d_hid, g_hid);

    const int* src = ei;
    const int* dst = ei + E;

    const int gemm_blocks = (N + 127) / 128;
    const int SMEM_MLP = (16384 + 2048 + 2048) * 4;   // 81920
    const int SMEM_L0  = (16384 + 1024 + 2048) * 4;   // 77824
    cudaFuncSetAttribute(fused_mlp_kernel, cudaFuncAttributeMaxDynamicSharedMemorySize, SMEM_MLP);
    cudaFuncSetAttribute(fused_l0_kernel,  cudaFuncAttributeMaxDynamicSharedMemorySize, SMEM_L0);

    // ---- layer 0 ----
    cudaMemsetAsync(d_agg, 0, (size_t)N * 8 * sizeof(float));
    scatter7_kernel<<<(E + 255) / 256, 256>>>(x, src, dst, d_agg, E);
    fused_l0_kernel<<<gemm_blocks, 256, SMEM_L0>>>(x, d_agg, w1[0], b1[0],
                                                   w2[0], b2[0], d_cat, 3 * H, N);

    // ---- layers 1, 2 ----
    for (int l = 1; l < 3; l++) {
        const float* h_prev = d_cat + (size_t)(l - 1) * H;  // row stride 384
        cudaMemsetAsync(d_agg, 0, (size_t)N * H * sizeof(float));
        int warps = (E + 3) / 4;
        scatter128_kernel<<<(warps * 32 + 255) / 256, 256>>>(h_prev, 3 * H, src, dst, d_agg, E);
        fused_mlp_kernel<<<gemm_blocks, 256, SMEM_MLP>>>(h_prev, 3 * H, d_agg,
                                                         w1[l], b1[l], w2[l], b2[l],
                                                         d_cat + (size_t)l * H, 3 * H, N);
    }

    // ---- global add pool ----
    cudaMemsetAsync(d_pool, 0, (size_t)NUM_GRAPHS * 384 * sizeof(float));
    pool_kernel<<<(N * 96 + 255) / 256, 256>>>(d_cat, batch, d_pool, N);

    // ---- classifier ----
    clf1_kernel<<<NUM_GRAPHS, 256>>>(d_pool, clf_w1, clf_b1, bn_g, bn_b, bn_m, bn_v, d_hid);
    clf2_kernel<<<(NUM_GRAPHS * 2 + 255) / 256, 256>>>(d_hid, clf_w2, clf_b2, out);
}